// round 13
// baseline (speedup 1.0000x reference)
#include <cuda_runtime.h>
#include <cuda_bf16.h>
#include <stdint.h>

#define D 128
#define NMAX 50000
#define EMAX 600000
#define AS 264              // padded bf16 stride ([hi|lo] 256 + 8 pad)
#define PREB 148            // preproc grid (all blocks co-resident)
#define TM 256              // GEMM block M tile

// ---------------- scratch (static device globals) ---------------------------
__device__ __align__(16) float g_hs [(size_t)NMAX * D];
__device__ __align__(16) float g_u  [(size_t)NMAX * D];
__device__ float g_dis[NMAX];
__device__ int   g_deg[NMAX];
__device__ int   g_cur[NMAX];
__device__ int   g_off[NMAX + 1];
__device__ unsigned int g_state[64];   // lookback scan state
__device__ unsigned int g_barc;        // monotonic grid-barrier counter
__device__ int   g_csr[EMAX];
// Weight images: B[n][k] bf16, hi at k 0..127, lo at k 128..255, stride AS
__device__ __align__(16) __nv_bfloat16 g_WtA[128 * AS];
__device__ __align__(16) __nv_bfloat16 g_WtB[128 * AS];

// ---------------- helpers ----------------------------------------------------
__device__ __forceinline__ uint32_t smem_u32(const void* p) {
    uint32_t a;
    asm("{ .reg .u64 t; cvta.to.shared.u64 t, %1; cvt.u32.u64 %0, t; }"
        : "=r"(a) : "l"(p));
    return a;
}
__device__ __forceinline__ void ldmx4(uint32_t* r, uint32_t addr) {
    asm volatile("ldmatrix.sync.aligned.m8n8.x4.shared.b16 {%0,%1,%2,%3}, [%4];"
                 : "=r"(r[0]), "=r"(r[1]), "=r"(r[2]), "=r"(r[3]) : "r"(addr));
}
__device__ __forceinline__ void mma16816(float* c, const uint32_t* a,
                                         const uint32_t* b) {
    asm volatile(
        "mma.sync.aligned.m16n8k16.row.col.f32.bf16.bf16.f32 "
        "{%0,%1,%2,%3}, {%4,%5,%6,%7}, {%8,%9}, {%0,%1,%2,%3};"
        : "+f"(c[0]), "+f"(c[1]), "+f"(c[2]), "+f"(c[3])
        : "r"(a[0]), "r"(a[1]), "r"(a[2]), "r"(a[3]), "r"(b[0]), "r"(b[1]));
}
// Software grid barrier with release semantics.
__device__ __forceinline__ void gbar(int nb) {
    __syncthreads();
    if (threadIdx.x == 0) {
        __threadfence();                        // release: drain writes to L2
        unsigned old = atomicAdd(&g_barc, 1u);
        unsigned target = (old / (unsigned)nb + 1u) * (unsigned)nb;
        while (atomicAdd(&g_barc, 0u) < target) {}
    }
    __syncthreads();
}

// ---------------- fused preprocessing: init+count+scan+fill ------------------
__global__ void __launch_bounds__(1024) k_pre(const float* __restrict__ W1,
                                              const float* __restrict__ W2,
                                              const int* __restrict__ src,
                                              const int* __restrict__ dst,
                                              int nN, int nE) {
    const int nb = gridDim.x;
    const int tid = threadIdx.x;
    const int gt = blockIdx.x * 1024 + tid;
    const int gstride = nb * 1024;

    // ---- Phase A: zero deg + scan state; split both weights ----
    for (int i = gt; i < nN; i += gstride) g_deg[i] = 0;
    if (gt < 64) g_state[gt] = 0u;
    for (int i = gt; i < 2 * D * D; i += gstride) {
        int which = i >= D * D;
        int j = which ? i - D * D : i;
        const float* W = which ? W2 : W1;
        __nv_bfloat16* img = which ? g_WtB : g_WtA;
        int k = j >> 7, n = j & 127;
        float x = W[k * D + n];
        __nv_bfloat16 hi = __float2bfloat16(x);
        __nv_bfloat16 lo = __float2bfloat16(x - __bfloat162float(hi));
        img[n * AS + k]       = hi;
        img[n * AS + 128 + k] = lo;
    }
    gbar(nb);

    // ---- Phase B: degree count (atomics, L2) ----
    for (int e = gt; e < nE; e += gstride) atomicAdd(&g_deg[dst[e]], 1);
    gbar(nb);

    // ---- Phase C: exclusive scan (decoupled lookback); .cg reads (L2) ----
    {
        __shared__ int sh[1024];
        __shared__ int s_excl;
        const int sb = (nN + 1023) / 1024;
        const int b = blockIdx.x;
        if (b < sb) {
            const int gi = b * 1024 + tid;
            int v = (gi < nN) ? __ldcg(&g_deg[gi]) : 0;   // bypass stale L1
            if (gi < nN) g_dis[gi] = rsqrtf((float)v + 1.0f);
            int val = v;
            sh[tid] = val;
            __syncthreads();
            #pragma unroll
            for (int off = 1; off < 1024; off <<= 1) {
                int t = (tid >= off) ? sh[tid - off] : 0;
                __syncthreads();
                val += t; sh[tid] = val;
                __syncthreads();
            }
            int total = sh[1023];

            if (tid == 0) {
                int excl = 0;
                if (b == 0) {
                    atomicExch(&g_state[0], (2u << 30) | (unsigned)total);
                } else {
                    atomicExch(&g_state[b], (1u << 30) | (unsigned)total);
                    int idx = b - 1;
                    while (idx >= 0) {
                        unsigned st = atomicAdd(&g_state[idx], 0u);
                        unsigned fl = st >> 30;
                        if (fl == 0u) continue;
                        excl += (int)(st & 0x3FFFFFFFu);
                        if (fl == 2u) break;
                        idx--;
                    }
                    atomicExch(&g_state[b], (2u << 30) | (unsigned)(excl + total));
                }
                s_excl = excl;
            }
            __syncthreads();
            int excl = s_excl;
            if (gi < nN) {
                int o = excl + val - v;
                g_off[gi] = o;
                g_cur[gi] = o;          // fill cursor starts at row offset
            }
            if (gi == nN - 1) g_off[nN] = excl + val;
        }
    }
    gbar(nb);

    // ---- Phase D: CSR fill ----
    for (int e = gt; e < nE; e += gstride) {
        int d = dst[e];
        int pos = atomicAdd(&g_cur[d], 1);
        g_csr[pos] = src[e];
    }
}

// ---------------- warp-MMA GEMM: g_hs[r,:] = (IN[r,:] @ W) * dis[r] ----------
// 512 threads; block tile 256x128; warp grid 8x2; warp tile 32x64;
// 24 K-steps of m16n8k16 over split-bf16 [hi|lo] operands.
// Smem: A 256xAS + B 128xAS = 202,752 B (1 CTA/SM, 16 warps = 4/SMSP).
__global__ void __launch_bounds__(512) k_gemm_mma(const float* __restrict__ Xext,
                                                  int useU, int whichW,
                                                  int nrows) {
    extern __shared__ __align__(16) __nv_bfloat16 sm[];
    __nv_bfloat16* Asm = sm;              // TM x AS
    __nv_bfloat16* Bsm = sm + TM * AS;    // 128 x AS

    const float* X = useU ? (const float*)g_u : Xext;
    const __nv_bfloat16* Wimg = whichW ? g_WtB : g_WtA;

    const int tid = threadIdx.x;
    const int wid = tid >> 5;
    const int lane = tid & 31;
    const int row0 = blockIdx.x * TM;

    // Copy weight image: 4224 float4 over 512 threads
    {
        const float4* src = (const float4*)Wimg;
        float4* dst = (float4*)Bsm;
        #pragma unroll
        for (int i = 0; i < 9; i++) {
            int idx = tid + i * 512;
            if (idx < (128 * AS * 2) / 16) dst[idx] = src[idx];
        }
    }
    // A: load f32 rows, split hi/lo, store [hi|lo] padded (TM*32 float4 / 512)
    {
        #pragma unroll
        for (int i = 0; i < TM * 32 / 512; i++) {   // 16 iters
            int idx = tid + i * 512;
            int r = idx >> 5;
            int c4 = idx & 31;
            float4 v = make_float4(0.f, 0.f, 0.f, 0.f);
            if (row0 + r < nrows)
                v = ((const float4*)(X + (size_t)(row0 + r) * D))[c4];
            int k = c4 * 4;
            __nv_bfloat16 hx = __float2bfloat16(v.x);
            __nv_bfloat16 hy = __float2bfloat16(v.y);
            __nv_bfloat16 hz = __float2bfloat16(v.z);
            __nv_bfloat16 hw = __float2bfloat16(v.w);
            __nv_bfloat16* ap = Asm + r * AS + k;
            *(__nv_bfloat162*)(ap)     = __halves2bfloat162(hx, hy);
            *(__nv_bfloat162*)(ap + 2) = __halves2bfloat162(hz, hw);
            __nv_bfloat162 lo01 = __floats2bfloat162_rn(
                v.x - __bfloat162float(hx), v.y - __bfloat162float(hy));
            __nv_bfloat162 lo23 = __floats2bfloat162_rn(
                v.z - __bfloat162float(hz), v.w - __bfloat162float(hw));
            *(__nv_bfloat162*)(ap + 128)     = lo01;
            *(__nv_bfloat162*)(ap + 128 + 2) = lo23;
        }
    }
    __syncthreads();

    const int warp_m = wid & 7;          // 8 warps along M (32 rows each)
    const int warp_n = wid >> 3;         // 2 warps along N (64 cols each)

    const int rowA = warp_m * 32 + (lane & 15);
    const int kAo  = (lane & 16) ? 8 : 0;
    const uint32_t aBase = smem_u32(Asm) + (uint32_t)(rowA * AS + kAo) * 2;
    const int nB   = warp_n * 64 + (lane & 7) + ((lane & 16) ? 8 : 0);
    const int kBo  = (lane & 8) ? 8 : 0;
    const uint32_t bBase = smem_u32(Bsm) + (uint32_t)(nB * AS + kBo) * 2;

    float acc[2][8][4];
    #pragma unroll
    for (int mt = 0; mt < 2; mt++)
        #pragma unroll
        for (int nt = 0; nt < 8; nt++)
            #pragma unroll
            for (int q = 0; q < 4; q++) acc[mt][nt][q] = 0.f;

    #pragma unroll
    for (int j = 0; j < 24; j++) {
        const int seg = j >> 3;
        const int o = (j & 7) * 16;
        const int ka = ((seg == 1) ? 128 : 0) + o;   // A: hi, lo, hi
        const int kb = ((seg == 2) ? 128 : 0) + o;   // B: hi, hi, lo

        uint32_t a[2][4];
        #pragma unroll
        for (int mt = 0; mt < 2; mt++)
            ldmx4(a[mt], aBase + (uint32_t)(mt * 16 * AS + ka) * 2);

        uint32_t b[8][2];
        #pragma unroll
        for (int p = 0; p < 4; p++) {
            uint32_t r[4];
            ldmx4(r, bBase + (uint32_t)(p * 16 * AS + kb) * 2);
            b[p * 2][0] = r[0]; b[p * 2][1] = r[1];
            b[p * 2 + 1][0] = r[2]; b[p * 2 + 1][1] = r[3];
        }

        #pragma unroll
        for (int mt = 0; mt < 2; mt++)
            #pragma unroll
            for (int nt = 0; nt < 8; nt++)
                mma16816(acc[mt][nt], a[mt], b[nt]);
    }

    // Epilogue: scale by dis[row], store float2 pairs
    #pragma unroll
    for (int mt = 0; mt < 2; mt++) {
        int rlo = row0 + warp_m * 32 + mt * 16 + (lane >> 2);
        int rhi = rlo + 8;
        float slo = (rlo < nrows) ? g_dis[rlo] : 0.f;
        float shi = (rhi < nrows) ? g_dis[rhi] : 0.f;
        #pragma unroll
        for (int nt = 0; nt < 8; nt++) {
            int col = warp_n * 64 + nt * 8 + 2 * (lane & 3);
            if (rlo < nrows)
                *(float2*)&g_hs[(size_t)rlo * D + col] =
                    make_float2(acc[mt][nt][0] * slo, acc[mt][nt][1] * slo);
            if (rhi < nrows)
                *(float2*)&g_hs[(size_t)rhi * D + col] =
                    make_float2(acc[mt][nt][2] * shi, acc[mt][nt][3] * shi);
        }
    }
}

// ---------------- fused gather + finalize (+LN+ReLU | output) ---------------
__global__ void __launch_bounds__(256) k_gather(const float* __restrict__ ori,
                                                const float* __restrict__ bias,
                                                const float* __restrict__ lw,
                                                const float* __restrict__ lb,
                                                float* __restrict__ out,
                                                int nN, int mode) {
    int idx = blockIdx.x * blockDim.x + threadIdx.x;
    int node = idx >> 5;
    if (node >= nN) return;
    const int lane = idx & 31;

    const int beg = g_off[node];
    const int end = g_off[node + 1];

    float4 a0 = make_float4(0.f, 0.f, 0.f, 0.f);
    float4 a1 = make_float4(0.f, 0.f, 0.f, 0.f);
    const float4* hs4 = (const float4*)g_hs;

    int e = beg;
    for (; e + 3 < end; e += 4) {
        int s0 = __ldg(&g_csr[e]);
        int s1 = __ldg(&g_csr[e + 1]);
        int s2 = __ldg(&g_csr[e + 2]);
        int s3 = __ldg(&g_csr[e + 3]);
        float4 v0 = hs4[(size_t)s0 * 32 + lane];
        float4 v1 = hs4[(size_t)s1 * 32 + lane];
        float4 v2 = hs4[(size_t)s2 * 32 + lane];
        float4 v3 = hs4[(size_t)s3 * 32 + lane];
        a0.x += v0.x; a0.y += v0.y; a0.z += v0.z; a0.w += v0.w;
        a1.x += v1.x; a1.y += v1.y; a1.z += v1.z; a1.w += v1.w;
        a0.x += v2.x; a0.y += v2.y; a0.z += v2.z; a0.w += v2.w;
        a1.x += v3.x; a1.y += v3.y; a1.z += v3.z; a1.w += v3.w;
    }
    for (; e < end; e++) {
        int s0 = __ldg(&g_csr[e]);
        float4 v0 = hs4[(size_t)s0 * 32 + lane];
        a0.x += v0.x; a0.y += v0.y; a0.z += v0.z; a0.w += v0.w;
    }
    float4 a = make_float4(a0.x + a1.x, a0.y + a1.y, a0.z + a1.z, a0.w + a1.w);

    float4 hv = hs4[(size_t)node * 32 + lane];   // self-loop term
    float s = g_dis[node];
    float4 bb = *(const float4*)(bias + lane * 4);

    float4 t;
    t.x = s * (a.x + hv.x) + bb.x;
    t.y = s * (a.y + hv.y) + bb.y;
    t.z = s * (a.z + hv.z) + bb.z;
    t.w = s * (a.w + hv.w) + bb.w;

    size_t base = (size_t)node * D + (size_t)lane * 4;

    if (mode == 1) {
        *(float4*)(out + base) = t;
        return;
    }

    float4 o = *(const float4*)(ori + base);     // residual
    t.x += o.x; t.y += o.y; t.z += o.z; t.w += o.w;

    float sum = t.x + t.y + t.z + t.w;
    float sq  = t.x * t.x + t.y * t.y + t.z * t.z + t.w * t.w;
    #pragma unroll
    for (int off = 16; off; off >>= 1) {
        sum += __shfl_xor_sync(0xFFFFFFFFu, sum, off);
        sq  += __shfl_xor_sync(0xFFFFFFFFu, sq,  off);
    }
    float mu  = sum * (1.0f / 128.0f);
    float var = sq * (1.0f / 128.0f) - mu * mu;
    float inv = rsqrtf(var + 1e-5f);

    float4 w   = *(const float4*)(lw + lane * 4);
    float4 lbv = *(const float4*)(lb + lane * 4);
    float4 u;
    u.x = fmaxf((t.x - mu) * inv * w.x + lbv.x, 0.f);
    u.y = fmaxf((t.y - mu) * inv * w.y + lbv.y, 0.f);
    u.z = fmaxf((t.z - mu) * inv * w.z + lbv.z, 0.f);
    u.w = fmaxf((t.w - mu) * inv * w.w + lbv.w, 0.f);
    *(float4*)(g_u + base) = u;
}

// ---------------------------------------------------------------------------
extern "C" void kernel_launch(void* const* d_in, const int* in_sizes, int n_in,
                              void* d_out, int out_size) {
    int iSrc, iDst, iW1, iB1, iW2, iB2, iL1w, iL1b, iL2w, iL2b;
    if (n_in >= 3 && in_sizes[1] == in_sizes[2] && in_sizes[1] > 100000) {
        iSrc = 1; iDst = 2; iW1 = 3; iB1 = 4; iW2 = 5; iB2 = 6;
        iL1w = 7; iL1b = 8; iL2w = 9; iL2b = 10;
    } else {
        iW1 = 1; iB1 = 2; iW2 = 3; iB2 = 4; iL1w = 5; iL1b = 6;
        iL2w = 7; iL2b = 8; iSrc = 9; iDst = 10;
    }

    const float* X   = (const float*)d_in[0];
    const int*   src = (const int*)d_in[iSrc];
    const int*   dst = (const int*)d_in[iDst];
    const float* W1  = (const float*)d_in[iW1];
    const float* b1  = (const float*)d_in[iB1];
    const float* W2  = (const float*)d_in[iW2];
    const float* b2  = (const float*)d_in[iB2];
    const float* l1w = (const float*)d_in[iL1w];
    const float* l1b = (const float*)d_in[iL1b];
    const float* l2w = (const float*)d_in[iL2w];
    const float* l2b = (const float*)d_in[iL2b];
    float* out = (float*)d_out;

    const int N = in_sizes[0] / D;
    const int E = in_sizes[iSrc];

    const int MMA_SMEM = (TM + 128) * AS * 2;  // 202,752 B
    cudaFuncSetAttribute(k_gemm_mma, cudaFuncAttributeMaxDynamicSharedMemorySize,
                         MMA_SMEM);

    const int T = 256;
    int gb = (N + TM - 1) / TM;
    int wb = ((N * 32) + T - 1) / T;

    // preprocessing: 1 persistent launch (init + count + scan + fill)
    k_pre<<<PREB, 1024>>>(W1, W2, src, dst, N, E);

    // conv 1 (W1, b1) + residual + LN1 + ReLU
    k_gemm_mma<<<gb, 512, MMA_SMEM>>>(X, 0, 0, N);
    k_gather  <<<wb, T>>>(X, b1, l1w, l1b, out, N, 0);

    // conv 2 (W2, b2) + residual + LN2 + ReLU
    k_gemm_mma<<<gb, 512, MMA_SMEM>>>(X, 1, 1, N);
    k_gather  <<<wb, T>>>(X, b2, l2w, l2b, out, N, 0);

    // conv 3 (W2, b2) -> output
    k_gemm_mma<<<gb, 512, MMA_SMEM>>>(X, 1, 1, N);
    k_gather  <<<wb, T>>>(X, b2, l2w, l2b, out, N, 1);
}

// round 14
// speedup vs baseline: 5.7635x; 5.7635x over previous
#include <cuda_runtime.h>
#include <cuda_bf16.h>
#include <stdint.h>

#define D 128
#define NMAX 50000
#define EMAX 600000
#define AS 264              // padded bf16 stride ([hi|lo] 256 + 8 pad)
#define PREB 148            // preproc grid (all blocks co-resident)
#define TM 64               // GEMM block M tile (2 CTAs/SM)

// ---------------- scratch (static device globals) ---------------------------
__device__ __align__(16) float g_hs [(size_t)NMAX * D];
__device__ __align__(16) float g_u  [(size_t)NMAX * D];
__device__ float g_dis[NMAX];
__device__ int   g_deg[NMAX];
__device__ int   g_cur[NMAX];
__device__ int   g_off[NMAX + 1];
__device__ unsigned int g_state[64];   // lookback scan state
__device__ unsigned int g_barc;        // monotonic grid-barrier counter
__device__ int   g_csr[EMAX];
// Weight images: B[n][k] bf16, hi at k 0..127, lo at k 128..255, stride AS
__device__ __align__(16) __nv_bfloat16 g_WtA[128 * AS];
__device__ __align__(16) __nv_bfloat16 g_WtB[128 * AS];

// ---------------- helpers ----------------------------------------------------
__device__ __forceinline__ uint32_t smem_u32(const void* p) {
    uint32_t a;
    asm("{ .reg .u64 t; cvta.to.shared.u64 t, %1; cvt.u32.u64 %0, t; }"
        : "=r"(a) : "l"(p));
    return a;
}
__device__ __forceinline__ void ldmx4(uint32_t* r, uint32_t addr) {
    asm volatile("ldmatrix.sync.aligned.m8n8.x4.shared.b16 {%0,%1,%2,%3}, [%4];"
                 : "=r"(r[0]), "=r"(r[1]), "=r"(r[2]), "=r"(r[3]) : "r"(addr));
}
__device__ __forceinline__ void mma16816(float* c, const uint32_t* a,
                                         const uint32_t* b) {
    asm volatile(
        "mma.sync.aligned.m16n8k16.row.col.f32.bf16.bf16.f32 "
        "{%0,%1,%2,%3}, {%4,%5,%6,%7}, {%8,%9}, {%0,%1,%2,%3};"
        : "+f"(c[0]), "+f"(c[1]), "+f"(c[2]), "+f"(c[3])
        : "r"(a[0]), "r"(a[1]), "r"(a[2]), "r"(a[3]), "r"(b[0]), "r"(b[1]));
}
// Software grid barrier with release semantics.
__device__ __forceinline__ void gbar(int nb) {
    __syncthreads();
    if (threadIdx.x == 0) {
        __threadfence();                        // release: drain writes to L2
        unsigned old = atomicAdd(&g_barc, 1u);
        unsigned target = (old / (unsigned)nb + 1u) * (unsigned)nb;
        while (atomicAdd(&g_barc, 0u) < target) {}
    }
    __syncthreads();
}

// ---------------- fused preprocessing: init+count+scan+fill ------------------
__global__ void __launch_bounds__(1024) k_pre(const float* __restrict__ W1,
                                              const float* __restrict__ W2,
                                              const int* __restrict__ src,
                                              const int* __restrict__ dst,
                                              int nN, int nE) {
    const int nb = gridDim.x;
    const int tid = threadIdx.x;
    const int gt = blockIdx.x * 1024 + tid;
    const int gstride = nb * 1024;

    // ---- Phase A: zero deg + scan state; split both weights ----
    for (int i = gt; i < nN; i += gstride) g_deg[i] = 0;
    if (gt < 64) g_state[gt] = 0u;
    for (int i = gt; i < 2 * D * D; i += gstride) {
        int which = i >= D * D;
        int j = which ? i - D * D : i;
        const float* W = which ? W2 : W1;
        __nv_bfloat16* img = which ? g_WtB : g_WtA;
        int k = j >> 7, n = j & 127;
        float x = W[k * D + n];
        __nv_bfloat16 hi = __float2bfloat16(x);
        __nv_bfloat16 lo = __float2bfloat16(x - __bfloat162float(hi));
        img[n * AS + k]       = hi;
        img[n * AS + 128 + k] = lo;
    }
    gbar(nb);

    // ---- Phase B: degree count (atomics, L2) ----
    for (int e = gt; e < nE; e += gstride) atomicAdd(&g_deg[dst[e]], 1);
    gbar(nb);

    // ---- Phase C: exclusive scan (decoupled lookback); .cg reads (L2) ----
    {
        __shared__ int sh[1024];
        __shared__ int s_excl;
        const int sb = (nN + 1023) / 1024;
        const int b = blockIdx.x;
        if (b < sb) {
            const int gi = b * 1024 + tid;
            int v = (gi < nN) ? __ldcg(&g_deg[gi]) : 0;   // bypass stale L1
            if (gi < nN) g_dis[gi] = rsqrtf((float)v + 1.0f);
            int val = v;
            sh[tid] = val;
            __syncthreads();
            #pragma unroll
            for (int off = 1; off < 1024; off <<= 1) {
                int t = (tid >= off) ? sh[tid - off] : 0;
                __syncthreads();
                val += t; sh[tid] = val;
                __syncthreads();
            }
            int total = sh[1023];

            if (tid == 0) {
                int excl = 0;
                if (b == 0) {
                    atomicExch(&g_state[0], (2u << 30) | (unsigned)total);
                } else {
                    atomicExch(&g_state[b], (1u << 30) | (unsigned)total);
                    int idx = b - 1;
                    while (idx >= 0) {
                        unsigned st = atomicAdd(&g_state[idx], 0u);
                        unsigned fl = st >> 30;
                        if (fl == 0u) continue;
                        excl += (int)(st & 0x3FFFFFFFu);
                        if (fl == 2u) break;
                        idx--;
                    }
                    atomicExch(&g_state[b], (2u << 30) | (unsigned)(excl + total));
                }
                s_excl = excl;
            }
            __syncthreads();
            int excl = s_excl;
            if (gi < nN) {
                int o = excl + val - v;
                g_off[gi] = o;
                g_cur[gi] = o;          // fill cursor starts at row offset
            }
            if (gi == nN - 1) g_off[nN] = excl + val;
        }
    }
    gbar(nb);

    // ---- Phase D: CSR fill ----
    for (int e = gt; e < nE; e += gstride) {
        int d = dst[e];
        int pos = atomicAdd(&g_cur[d], 1);
        g_csr[pos] = src[e];
    }
}

// ---------------- warp-MMA GEMM: g_hs[r,:] = (IN[r,:] @ W) * dis[r] ----------
// 128 threads; block tile 64x128; warp grid 2x2; warp tile 32x64 (R11 ratio);
// smem A 64xAS + B 128xAS = 101.4 KB -> 2 CTAs/SM (prologue/MMA overlap).
__global__ void __launch_bounds__(128) k_gemm_mma(const float* __restrict__ Xext,
                                                  int useU, int whichW,
                                                  int nrows) {
    extern __shared__ __align__(16) __nv_bfloat16 sm[];
    __nv_bfloat16* Asm = sm;              // TM x AS
    __nv_bfloat16* Bsm = sm + TM * AS;    // 128 x AS

    const float* X = useU ? (const float*)g_u : Xext;
    const __nv_bfloat16* Wimg = whichW ? g_WtB : g_WtA;

    const int tid = threadIdx.x;
    const int wid = tid >> 5;
    const int lane = tid & 31;
    const int row0 = blockIdx.x * TM;

    // Copy weight image: 4224 float4 over 128 threads = 33 each
    {
        const float4* src = (const float4*)Wimg;
        float4* dst = (float4*)Bsm;
        #pragma unroll
        for (int i = 0; i < 33; i++) {
            int idx = tid + i * 128;
            dst[idx] = src[idx];
        }
    }
    // A: load f32 rows, split hi/lo, store [hi|lo] padded (TM*32 f4 / 128 = 16)
    {
        #pragma unroll
        for (int i = 0; i < TM * 32 / 128; i++) {
            int idx = tid + i * 128;
            int r = idx >> 5;
            int c4 = idx & 31;
            float4 v = make_float4(0.f, 0.f, 0.f, 0.f);
            if (row0 + r < nrows)
                v = ((const float4*)(X + (size_t)(row0 + r) * D))[c4];
            int k = c4 * 4;
            __nv_bfloat16 hx = __float2bfloat16(v.x);
            __nv_bfloat16 hy = __float2bfloat16(v.y);
            __nv_bfloat16 hz = __float2bfloat16(v.z);
            __nv_bfloat16 hw = __float2bfloat16(v.w);
            __nv_bfloat16* ap = Asm + r * AS + k;
            *(__nv_bfloat162*)(ap)     = __halves2bfloat162(hx, hy);
            *(__nv_bfloat162*)(ap + 2) = __halves2bfloat162(hz, hw);
            __nv_bfloat162 lo01 = __floats2bfloat162_rn(
                v.x - __bfloat162float(hx), v.y - __bfloat162float(hy));
            __nv_bfloat162 lo23 = __floats2bfloat162_rn(
                v.z - __bfloat162float(hz), v.w - __bfloat162float(hw));
            *(__nv_bfloat162*)(ap + 128)     = lo01;
            *(__nv_bfloat162*)(ap + 128 + 2) = lo23;
        }
    }
    __syncthreads();

    const int warp_m = wid & 1;          // 2 warps along M (32 rows each)
    const int warp_n = wid >> 1;         // 2 warps along N (64 cols each)

    const int rowA = warp_m * 32 + (lane & 15);
    const int kAo  = (lane & 16) ? 8 : 0;
    const uint32_t aBase = smem_u32(Asm) + (uint32_t)(rowA * AS + kAo) * 2;
    const int nB   = warp_n * 64 + (lane & 7) + ((lane & 16) ? 8 : 0);
    const int kBo  = (lane & 8) ? 8 : 0;
    const uint32_t bBase = smem_u32(Bsm) + (uint32_t)(nB * AS + kBo) * 2;

    float acc[2][8][4];
    #pragma unroll
    for (int mt = 0; mt < 2; mt++)
        #pragma unroll
        for (int nt = 0; nt < 8; nt++)
            #pragma unroll
            for (int q = 0; q < 4; q++) acc[mt][nt][q] = 0.f;

    #pragma unroll
    for (int j = 0; j < 24; j++) {
        const int seg = j >> 3;
        const int o = (j & 7) * 16;
        const int ka = ((seg == 1) ? 128 : 0) + o;   // A: hi, lo, hi
        const int kb = ((seg == 2) ? 128 : 0) + o;   // B: hi, hi, lo

        uint32_t a[2][4];
        #pragma unroll
        for (int mt = 0; mt < 2; mt++)
            ldmx4(a[mt], aBase + (uint32_t)(mt * 16 * AS + ka) * 2);

        uint32_t b[8][2];
        #pragma unroll
        for (int p = 0; p < 4; p++) {
            uint32_t r[4];
            ldmx4(r, bBase + (uint32_t)(p * 16 * AS + kb) * 2);
            b[p * 2][0] = r[0]; b[p * 2][1] = r[1];
            b[p * 2 + 1][0] = r[2]; b[p * 2 + 1][1] = r[3];
        }

        #pragma unroll
        for (int mt = 0; mt < 2; mt++)
            #pragma unroll
            for (int nt = 0; nt < 8; nt++)
                mma16816(acc[mt][nt], a[mt], b[nt]);
    }

    // Epilogue: scale by dis[row], store float2 pairs
    #pragma unroll
    for (int mt = 0; mt < 2; mt++) {
        int rlo = row0 + warp_m * 32 + mt * 16 + (lane >> 2);
        int rhi = rlo + 8;
        float slo = (rlo < nrows) ? g_dis[rlo] : 0.f;
        float shi = (rhi < nrows) ? g_dis[rhi] : 0.f;
        #pragma unroll
        for (int nt = 0; nt < 8; nt++) {
            int col = warp_n * 64 + nt * 8 + 2 * (lane & 3);
            if (rlo < nrows)
                *(float2*)&g_hs[(size_t)rlo * D + col] =
                    make_float2(acc[mt][nt][0] * slo, acc[mt][nt][1] * slo);
            if (rhi < nrows)
                *(float2*)&g_hs[(size_t)rhi * D + col] =
                    make_float2(acc[mt][nt][2] * shi, acc[mt][nt][3] * shi);
        }
    }
}

// ---------------- fused gather + finalize (+LN+ReLU | output) ---------------
__global__ void __launch_bounds__(256) k_gather(const float* __restrict__ ori,
                                                const float* __restrict__ bias,
                                                const float* __restrict__ lw,
                                                const float* __restrict__ lb,
                                                float* __restrict__ out,
                                                int nN, int mode) {
    int idx = blockIdx.x * blockDim.x + threadIdx.x;
    int node = idx >> 5;
    if (node >= nN) return;
    const int lane = idx & 31;

    const int beg = g_off[node];
    const int end = g_off[node + 1];

    float4 a0 = make_float4(0.f, 0.f, 0.f, 0.f);
    float4 a1 = make_float4(0.f, 0.f, 0.f, 0.f);
    const float4* hs4 = (const float4*)g_hs;

    int e = beg;
    for (; e + 3 < end; e += 4) {
        int s0 = __ldg(&g_csr[e]);
        int s1 = __ldg(&g_csr[e + 1]);
        int s2 = __ldg(&g_csr[e + 2]);
        int s3 = __ldg(&g_csr[e + 3]);
        float4 v0 = hs4[(size_t)s0 * 32 + lane];
        float4 v1 = hs4[(size_t)s1 * 32 + lane];
        float4 v2 = hs4[(size_t)s2 * 32 + lane];
        float4 v3 = hs4[(size_t)s3 * 32 + lane];
        a0.x += v0.x; a0.y += v0.y; a0.z += v0.z; a0.w += v0.w;
        a1.x += v1.x; a1.y += v1.y; a1.z += v1.z; a1.w += v1.w;
        a0.x += v2.x; a0.y += v2.y; a0.z += v2.z; a0.w += v2.w;
        a1.x += v3.x; a1.y += v3.y; a1.z += v3.z; a1.w += v3.w;
    }
    for (; e < end; e++) {
        int s0 = __ldg(&g_csr[e]);
        float4 v0 = hs4[(size_t)s0 * 32 + lane];
        a0.x += v0.x; a0.y += v0.y; a0.z += v0.z; a0.w += v0.w;
    }
    float4 a = make_float4(a0.x + a1.x, a0.y + a1.y, a0.z + a1.z, a0.w + a1.w);

    float4 hv = hs4[(size_t)node * 32 + lane];   // self-loop term
    float s = g_dis[node];
    float4 bb = *(const float4*)(bias + lane * 4);

    float4 t;
    t.x = s * (a.x + hv.x) + bb.x;
    t.y = s * (a.y + hv.y) + bb.y;
    t.z = s * (a.z + hv.z) + bb.z;
    t.w = s * (a.w + hv.w) + bb.w;

    size_t base = (size_t)node * D + (size_t)lane * 4;

    if (mode == 1) {
        *(float4*)(out + base) = t;
        return;
    }

    float4 o = *(const float4*)(ori + base);     // residual
    t.x += o.x; t.y += o.y; t.z += o.z; t.w += o.w;

    float sum = t.x + t.y + t.z + t.w;
    float sq  = t.x * t.x + t.y * t.y + t.z * t.z + t.w * t.w;
    #pragma unroll
    for (int off = 16; off; off >>= 1) {
        sum += __shfl_xor_sync(0xFFFFFFFFu, sum, off);
        sq  += __shfl_xor_sync(0xFFFFFFFFu, sq,  off);
    }
    float mu  = sum * (1.0f / 128.0f);
    float var = sq * (1.0f / 128.0f) - mu * mu;
    float inv = rsqrtf(var + 1e-5f);

    float4 w   = *(const float4*)(lw + lane * 4);
    float4 lbv = *(const float4*)(lb + lane * 4);
    float4 u;
    u.x = fmaxf((t.x - mu) * inv * w.x + lbv.x, 0.f);
    u.y = fmaxf((t.y - mu) * inv * w.y + lbv.y, 0.f);
    u.z = fmaxf((t.z - mu) * inv * w.z + lbv.z, 0.f);
    u.w = fmaxf((t.w - mu) * inv * w.w + lbv.w, 0.f);
    *(float4*)(g_u + base) = u;
}

// ---------------------------------------------------------------------------
extern "C" void kernel_launch(void* const* d_in, const int* in_sizes, int n_in,
                              void* d_out, int out_size) {
    int iSrc, iDst, iW1, iB1, iW2, iB2, iL1w, iL1b, iL2w, iL2b;
    if (n_in >= 3 && in_sizes[1] == in_sizes[2] && in_sizes[1] > 100000) {
        iSrc = 1; iDst = 2; iW1 = 3; iB1 = 4; iW2 = 5; iB2 = 6;
        iL1w = 7; iL1b = 8; iL2w = 9; iL2b = 10;
    } else {
        iW1 = 1; iB1 = 2; iW2 = 3; iB2 = 4; iL1w = 5; iL1b = 6;
        iL2w = 7; iL2b = 8; iSrc = 9; iDst = 10;
    }

    const float* X   = (const float*)d_in[0];
    const int*   src = (const int*)d_in[iSrc];
    const int*   dst = (const int*)d_in[iDst];
    const float* W1  = (const float*)d_in[iW1];
    const float* b1  = (const float*)d_in[iB1];
    const float* W2  = (const float*)d_in[iW2];
    const float* b2  = (const float*)d_in[iB2];
    const float* l1w = (const float*)d_in[iL1w];
    const float* l1b = (const float*)d_in[iL1b];
    const float* l2w = (const float*)d_in[iL2w];
    const float* l2b = (const float*)d_in[iL2b];
    float* out = (float*)d_out;

    const int N = in_sizes[0] / D;
    const int E = in_sizes[iSrc];

    const int MMA_SMEM = (TM + 128) * AS * 2;  // 101,376 B -> 2 CTAs/SM
    cudaFuncSetAttribute(k_gemm_mma, cudaFuncAttributeMaxDynamicSharedMemorySize,
                         MMA_SMEM);

    const int T = 256;
    int gb = (N + TM - 1) / TM;
    int wb = ((N * 32) + T - 1) / T;

    // preprocessing: 1 persistent launch (init + count + scan + fill)
    k_pre<<<PREB, 1024>>>(W1, W2, src, dst, N, E);

    // conv 1 (W1, b1) + residual + LN1 + ReLU
    k_gemm_mma<<<gb, 128, MMA_SMEM>>>(X, 0, 0, N);
    k_gather  <<<wb, T>>>(X, b1, l1w, l1b, out, N, 0);

    // conv 2 (W2, b2) + residual + LN2 + ReLU
    k_gemm_mma<<<gb, 128, MMA_SMEM>>>(X, 1, 1, N);
    k_gather  <<<wb, T>>>(X, b2, l2w, l2b, out, N, 0);

    // conv 3 (W2, b2) -> output
    k_gemm_mma<<<gb, 128, MMA_SMEM>>>(X, 1, 1, N);
    k_gather  <<<wb, T>>>(X, b2, l2w, l2b, out, N, 1);
}

// round 15
// speedup vs baseline: 6.5182x; 1.1309x over previous
#include <cuda_runtime.h>
#include <cuda_bf16.h>
#include <cuda_fp16.h>
#include <stdint.h>

#define D 128
#define NMAX 50000
#define EMAX 600000
#define AS 264              // padded bf16 stride ([hi|lo] 256 + 8 pad)

// ---------------- scratch (static device globals) ---------------------------
__device__ __align__(16) __half g_hs [(size_t)NMAX * D];   // fp16 conv output
__device__ __align__(16) float  g_u  [(size_t)NMAX * D];
__device__ float g_dis[NMAX];
__device__ int   g_deg[NMAX];
__device__ int   g_cur[NMAX];
__device__ int   g_off[NMAX + 1];
__device__ unsigned int g_state[64];   // lookback scan state
__device__ int   g_csr[EMAX];
// Weight images: B[n][k] bf16, hi at k 0..127, lo at k 128..255, stride AS
__device__ __align__(16) __nv_bfloat16 g_WtA[128 * AS];
__device__ __align__(16) __nv_bfloat16 g_WtB[128 * AS];

// ---------------- helpers ----------------------------------------------------
__device__ __forceinline__ uint32_t smem_u32(const void* p) {
    uint32_t a;
    asm("{ .reg .u64 t; cvta.to.shared.u64 t, %1; cvt.u32.u64 %0, t; }"
        : "=r"(a) : "l"(p));
    return a;
}
__device__ __forceinline__ void ldmx4(uint32_t* r, uint32_t addr) {
    asm volatile("ldmatrix.sync.aligned.m8n8.x4.shared.b16 {%0,%1,%2,%3}, [%4];"
                 : "=r"(r[0]), "=r"(r[1]), "=r"(r[2]), "=r"(r[3]) : "r"(addr));
}
__device__ __forceinline__ void mma16816(float* c, const uint32_t* a,
                                         const uint32_t* b) {
    asm volatile(
        "mma.sync.aligned.m16n8k16.row.col.f32.bf16.bf16.f32 "
        "{%0,%1,%2,%3}, {%4,%5,%6,%7}, {%8,%9}, {%0,%1,%2,%3};"
        : "+f"(c[0]), "+f"(c[1]), "+f"(c[2]), "+f"(c[3])
        : "r"(a[0]), "r"(a[1]), "r"(a[2]), "r"(a[3]), "r"(b[0]), "r"(b[1]));
}

// ---------------- init: zero deg/cur/state + split both weights --------------
__global__ void __launch_bounds__(256) k_init(const float* __restrict__ W1,
                                              const float* __restrict__ W2,
                                              int nN) {
    int stride = gridDim.x * blockDim.x;
    int t0 = blockIdx.x * blockDim.x + threadIdx.x;
    for (int i = t0; i < nN; i += stride) {
        g_deg[i] = 0;
        g_cur[i] = 0;
    }
    if (t0 < 64) g_state[t0] = 0u;
    for (int i = t0; i < 2 * D * D; i += stride) {
        int which = i >= D * D;
        int j = which ? i - D * D : i;
        const float* W = which ? W2 : W1;
        __nv_bfloat16* img = which ? g_WtB : g_WtA;
        int k = j >> 7, n = j & 127;
        float x = W[k * D + n];
        __nv_bfloat16 hi = __float2bfloat16(x);
        __nv_bfloat16 lo = __float2bfloat16(x - __bfloat162float(hi));
        img[n * AS + k]       = hi;
        img[n * AS + 128 + k] = lo;
    }
}

__global__ void k_count(const int* __restrict__ dst, int nE) {
    int e = blockIdx.x * blockDim.x + threadIdx.x;
    if (e < nE) atomicAdd(&g_deg[dst[e]], 1);
}

// ---------------- single-kernel exclusive scan (decoupled lookback) ----------
__global__ void __launch_bounds__(1024) k_scan(int nN) {
    __shared__ int sh[1024];
    __shared__ int s_excl;
    const int tid = threadIdx.x;
    const int b = blockIdx.x;
    const int gi = b * 1024 + tid;
    int v = (gi < nN) ? g_deg[gi] : 0;
    if (gi < nN) g_dis[gi] = rsqrtf((float)v + 1.0f);
    int val = v;
    sh[tid] = val;
    __syncthreads();
    #pragma unroll
    for (int off = 1; off < 1024; off <<= 1) {
        int t = (tid >= off) ? sh[tid - off] : 0;
        __syncthreads();
        val += t; sh[tid] = val;
        __syncthreads();
    }
    int total = sh[1023];

    if (tid == 0) {
        int excl = 0;
        if (b == 0) {
            atomicExch(&g_state[0], (2u << 30) | (unsigned)total);
        } else {
            atomicExch(&g_state[b], (1u << 30) | (unsigned)total);
            int idx = b - 1;
            while (idx >= 0) {
                unsigned st = atomicAdd(&g_state[idx], 0u);
                unsigned fl = st >> 30;
                if (fl == 0u) continue;
                excl += (int)(st & 0x3FFFFFFFu);
                if (fl == 2u) break;
                idx--;
            }
            atomicExch(&g_state[b], (2u << 30) | (unsigned)(excl + total));
        }
        s_excl = excl;
    }
    __syncthreads();
    int excl = s_excl;
    if (gi < nN) {
        int o = excl + val - v;
        g_off[gi] = o;
        g_cur[gi] = o;           // pre-seed fill cursor
    }
    if (gi == nN - 1) g_off[nN] = excl + val;
}

__global__ void k_fill(const int* __restrict__ src, const int* __restrict__ dst,
                       int nE) {
    int e = blockIdx.x * blockDim.x + threadIdx.x;
    if (e >= nE) return;
    int d = dst[e];
    int pos = atomicAdd(&g_cur[d], 1);
    g_csr[pos] = src[e];
}

// ---------------- warp-MMA GEMM: g_hs[r,:] = fp16((IN[r,:] @ W) * dis[r]) ----
// 256 threads; block tile 128x128; warp tile 32x64 (4x2 warps);
// 24 K-steps of m16n8k16 over split-bf16 [hi|lo] operands. (R11 config)
__global__ void __launch_bounds__(256) k_gemm_mma(const float* __restrict__ Xext,
                                                  int useU, int whichW,
                                                  int nrows) {
    extern __shared__ __align__(16) __nv_bfloat16 sm[];
    __nv_bfloat16* Asm = sm;              // 128 x AS
    __nv_bfloat16* Bsm = sm + 128 * AS;   // 128 x AS

    const float* X = useU ? (const float*)g_u : Xext;
    const __nv_bfloat16* Wimg = whichW ? g_WtB : g_WtA;

    const int tid = threadIdx.x;
    const int wid = tid >> 5;
    const int lane = tid & 31;
    const int row0 = blockIdx.x * 128;

    // Copy weight image: 4224 float4
    {
        const float4* src = (const float4*)Wimg;
        float4* dst = (float4*)Bsm;
        #pragma unroll
        for (int i = 0; i < 17; i++) {
            int idx = tid + i * 256;
            if (idx < (128 * AS * 2) / 16) dst[idx] = src[idx];
        }
    }
    // A: load f32 rows, split hi/lo, store [hi|lo] padded
    {
        #pragma unroll
        for (int i = 0; i < 16; i++) {
            int idx = tid + i * 256;
            int r = idx >> 5;
            int c4 = idx & 31;
            float4 v = make_float4(0.f, 0.f, 0.f, 0.f);
            if (row0 + r < nrows)
                v = ((const float4*)(X + (size_t)(row0 + r) * D))[c4];
            int k = c4 * 4;
            __nv_bfloat16 hx = __float2bfloat16(v.x);
            __nv_bfloat16 hy = __float2bfloat16(v.y);
            __nv_bfloat16 hz = __float2bfloat16(v.z);
            __nv_bfloat16 hw = __float2bfloat16(v.w);
            __nv_bfloat16* ap = Asm + r * AS + k;
            *(__nv_bfloat162*)(ap)     = __halves2bfloat162(hx, hy);
            *(__nv_bfloat162*)(ap + 2) = __halves2bfloat162(hz, hw);
            __nv_bfloat162 lo01 = __floats2bfloat162_rn(
                v.x - __bfloat162float(hx), v.y - __bfloat162float(hy));
            __nv_bfloat162 lo23 = __floats2bfloat162_rn(
                v.z - __bfloat162float(hz), v.w - __bfloat162float(hw));
            *(__nv_bfloat162*)(ap + 128)     = lo01;
            *(__nv_bfloat162*)(ap + 128 + 2) = lo23;
        }
    }
    __syncthreads();

    const int warp_m = wid & 3;          // 4 warps along M (32 rows each)
    const int warp_n = wid >> 2;         // 2 warps along N (64 cols each)

    const int rowA = warp_m * 32 + (lane & 15);
    const int kAo  = (lane & 16) ? 8 : 0;
    const uint32_t aBase = smem_u32(Asm) + (uint32_t)(rowA * AS + kAo) * 2;
    const int nB   = warp_n * 64 + (lane & 7) + ((lane & 16) ? 8 : 0);
    const int kBo  = (lane & 8) ? 8 : 0;
    const uint32_t bBase = smem_u32(Bsm) + (uint32_t)(nB * AS + kBo) * 2;

    float acc[2][8][4];
    #pragma unroll
    for (int mt = 0; mt < 2; mt++)
        #pragma unroll
        for (int nt = 0; nt < 8; nt++)
            #pragma unroll
            for (int q = 0; q < 4; q++) acc[mt][nt][q] = 0.f;

    #pragma unroll
    for (int j = 0; j < 24; j++) {
        const int seg = j >> 3;
        const int o = (j & 7) * 16;
        const int ka = ((seg == 1) ? 128 : 0) + o;   // A: hi, lo, hi
        const int kb = ((seg == 2) ? 128 : 0) + o;   // B: hi, hi, lo

        uint32_t a[2][4];
        #pragma unroll
        for (int mt = 0; mt < 2; mt++)
            ldmx4(a[mt], aBase + (uint32_t)(mt * 16 * AS + ka) * 2);

        uint32_t b[8][2];
        #pragma unroll
        for (int p = 0; p < 4; p++) {
            uint32_t r[4];
            ldmx4(r, bBase + (uint32_t)(p * 16 * AS + kb) * 2);
            b[p * 2][0] = r[0]; b[p * 2][1] = r[1];
            b[p * 2 + 1][0] = r[2]; b[p * 2 + 1][1] = r[3];
        }

        #pragma unroll
        for (int mt = 0; mt < 2; mt++)
            #pragma unroll
            for (int nt = 0; nt < 8; nt++)
                mma16816(acc[mt][nt], a[mt], b[nt]);
    }

    // Epilogue: scale by dis[row], store fp16 pairs
    #pragma unroll
    for (int mt = 0; mt < 2; mt++) {
        int rlo = row0 + warp_m * 32 + mt * 16 + (lane >> 2);
        int rhi = rlo + 8;
        float slo = (rlo < nrows) ? g_dis[rlo] : 0.f;
        float shi = (rhi < nrows) ? g_dis[rhi] : 0.f;
        #pragma unroll
        for (int nt = 0; nt < 8; nt++) {
            int col = warp_n * 64 + nt * 8 + 2 * (lane & 3);
            if (rlo < nrows)
                *(__half2*)&g_hs[(size_t)rlo * D + col] =
                    __floats2half2_rn(acc[mt][nt][0] * slo, acc[mt][nt][1] * slo);
            if (rhi < nrows)
                *(__half2*)&g_hs[(size_t)rhi * D + col] =
                    __floats2half2_rn(acc[mt][nt][2] * shi, acc[mt][nt][3] * shi);
        }
    }
}

// ---------------- fused gather + finalize (+LN+ReLU | output) ---------------
// One warp per node; lane owns 4 consecutive cols (4 halves = uint2 per row).
__global__ void __launch_bounds__(256) k_gather(const float* __restrict__ ori,
                                                const float* __restrict__ bias,
                                                const float* __restrict__ lw,
                                                const float* __restrict__ lb,
                                                float* __restrict__ out,
                                                int nN, int mode) {
    int idx = blockIdx.x * blockDim.x + threadIdx.x;
    int node = idx >> 5;
    if (node >= nN) return;
    const int lane = idx & 31;

    const int beg = g_off[node];
    const int end = g_off[node + 1];

    float4 a0 = make_float4(0.f, 0.f, 0.f, 0.f);
    float4 a1 = make_float4(0.f, 0.f, 0.f, 0.f);
    const uint2* hsu = (const uint2*)g_hs;   // 4 halves per lane per row

    #define ACC_H(accv, q)  do {                                   \
        float2 f01 = __half22float2(*(const __half2*)&(q).x);      \
        float2 f23 = __half22float2(*(const __half2*)&(q).y);      \
        (accv).x += f01.x; (accv).y += f01.y;                      \
        (accv).z += f23.x; (accv).w += f23.y; } while (0)

    int e = beg;
    for (; e + 3 < end; e += 4) {
        int s0 = __ldg(&g_csr[e]);
        int s1 = __ldg(&g_csr[e + 1]);
        int s2 = __ldg(&g_csr[e + 2]);
        int s3 = __ldg(&g_csr[e + 3]);
        uint2 q0 = hsu[(size_t)s0 * 32 + lane];
        uint2 q1 = hsu[(size_t)s1 * 32 + lane];
        uint2 q2 = hsu[(size_t)s2 * 32 + lane];
        uint2 q3 = hsu[(size_t)s3 * 32 + lane];
        ACC_H(a0, q0);
        ACC_H(a1, q1);
        ACC_H(a0, q2);
        ACC_H(a1, q3);
    }
    for (; e < end; e++) {
        int s0 = __ldg(&g_csr[e]);
        uint2 q0 = hsu[(size_t)s0 * 32 + lane];
        ACC_H(a0, q0);
    }
    float4 a = make_float4(a0.x + a1.x, a0.y + a1.y, a0.z + a1.z, a0.w + a1.w);

    // self-loop term
    uint2 qh = hsu[(size_t)node * 32 + lane];
    float2 h01 = __half22float2(*(const __half2*)&qh.x);
    float2 h23 = __half22float2(*(const __half2*)&qh.y);

    float s = g_dis[node];
    float4 bb = *(const float4*)(bias + lane * 4);

    float4 t;
    t.x = s * (a.x + h01.x) + bb.x;
    t.y = s * (a.y + h01.y) + bb.y;
    t.z = s * (a.z + h23.x) + bb.z;
    t.w = s * (a.w + h23.y) + bb.w;

    size_t base = (size_t)node * D + (size_t)lane * 4;

    if (mode == 1) {
        *(float4*)(out + base) = t;
        return;
    }

    float4 o = *(const float4*)(ori + base);     // residual
    t.x += o.x; t.y += o.y; t.z += o.z; t.w += o.w;

    float sum = t.x + t.y + t.z + t.w;
    float sq  = t.x * t.x + t.y * t.y + t.z * t.z + t.w * t.w;
    #pragma unroll
    for (int off = 16; off; off >>= 1) {
        sum += __shfl_xor_sync(0xFFFFFFFFu, sum, off);
        sq  += __shfl_xor_sync(0xFFFFFFFFu, sq,  off);
    }
    float mu  = sum * (1.0f / 128.0f);
    float var = sq * (1.0f / 128.0f) - mu * mu;
    float inv = rsqrtf(var + 1e-5f);

    float4 w   = *(const float4*)(lw + lane * 4);
    float4 lbv = *(const float4*)(lb + lane * 4);
    float4 u;
    u.x = fmaxf((t.x - mu) * inv * w.x + lbv.x, 0.f);
    u.y = fmaxf((t.y - mu) * inv * w.y + lbv.y, 0.f);
    u.z = fmaxf((t.z - mu) * inv * w.z + lbv.z, 0.f);
    u.w = fmaxf((t.w - mu) * inv * w.w + lbv.w, 0.f);
    *(float4*)(g_u + base) = u;
}

// ---------------------------------------------------------------------------
extern "C" void kernel_launch(void* const* d_in, const int* in_sizes, int n_in,
                              void* d_out, int out_size) {
    int iSrc, iDst, iW1, iB1, iW2, iB2, iL1w, iL1b, iL2w, iL2b;
    if (n_in >= 3 && in_sizes[1] == in_sizes[2] && in_sizes[1] > 100000) {
        iSrc = 1; iDst = 2; iW1 = 3; iB1 = 4; iW2 = 5; iB2 = 6;
        iL1w = 7; iL1b = 8; iL2w = 9; iL2b = 10;
    } else {
        iW1 = 1; iB1 = 2; iW2 = 3; iB2 = 4; iL1w = 5; iL1b = 6;
        iL2w = 7; iL2b = 8; iSrc = 9; iDst = 10;
    }

    const float* X   = (const float*)d_in[0];
    const int*   src = (const int*)d_in[iSrc];
    const int*   dst = (const int*)d_in[iDst];
    const float* W1  = (const float*)d_in[iW1];
    const float* b1  = (const float*)d_in[iB1];
    const float* W2  = (const float*)d_in[iW2];
    const float* b2  = (const float*)d_in[iB2];
    const float* l1w = (const float*)d_in[iL1w];
    const float* l1b = (const float*)d_in[iL1b];
    const float* l2w = (const float*)d_in[iL2w];
    const float* l2b = (const float*)d_in[iL2b];
    float* out = (float*)d_out;

    const int N = in_sizes[0] / D;
    const int E = in_sizes[iSrc];

    const int MMA_SMEM = 2 * 128 * AS * 2;  // 135168 B
    cudaFuncSetAttribute(k_gemm_mma, cudaFuncAttributeMaxDynamicSharedMemorySize,
                         MMA_SMEM);

    const int T = 256;
    int cb = (E + T - 1) / T;
    int gb = (N + 127) / 128;
    int wb = ((N * 32) + T - 1) / T;
    int sb = (N + 1023) / 1024;

    // preprocessing: 4 launches
    k_init <<<200, T>>>(W1, W2, N);
    k_count<<<cb, T>>>(dst, E);
    k_scan <<<sb, 1024>>>(N);
    k_fill <<<cb, T>>>(src, dst, E);

    // conv 1 (W1, b1) + residual + LN1 + ReLU
    k_gemm_mma<<<gb, T, MMA_SMEM>>>(X, 0, 0, N);
    k_gather  <<<wb, T>>>(X, b1, l1w, l1b, out, N, 0);

    // conv 2 (W2, b2) + residual + LN2 + ReLU
    k_gemm_mma<<<gb, T, MMA_SMEM>>>(X, 1, 1, N);
    k_gather  <<<wb, T>>>(X, b2, l2w, l2b, out, N, 0);

    // conv 3 (W2, b2) -> output
    k_gemm_mma<<<gb, T, MMA_SMEM>>>(X, 1, 1, N);
    k_gather  <<<wb, T>>>(X, b2, l2w, l2b, out, N, 1);
}